// round 1
// baseline (speedup 1.0000x reference)
#include <cuda_runtime.h>

#define Bb 2
#define Nn 128
#define Cc 256
#define BN2 (Bb*Nn*Nn)        // 32768 edge rows
#define NODES_SZ (Bb*Nn*Cc)   // 65536
#define EDGES_SZ (BN2*Cc)     // 8388608
#define KN_ 101
#define KE_ 7
#define ALPHA 0.2f
#define LN_EPS 1e-5f
#define NEG_BIG (-1e30f)

// ---------------- scratch (device globals: allocation-free) ----------------
__device__ float g_eA[EDGES_SZ];
__device__ float g_eB[EDGES_SZ];
__device__ float g_n0[NODES_SZ];
__device__ float g_n1[NODES_SZ];
__device__ float g_ai[NODES_SZ];
__device__ float g_aj[NODES_SZ];
__device__ float g_nf[NODES_SZ];
__device__ float g_s[Bb*Nn];
__device__ float g_v[Cc];
__device__ float g_w[Cc];
__device__ float g_dotv[BN2];

// ---------------- small generic GEMM: out[m,n] = A[m,:]·W[n,:] + bias ------
__global__ void gemm_small(const float* __restrict__ A, const float* __restrict__ W,
                           const float* __restrict__ bias, float* __restrict__ out,
                           int M, int N, int K, int ldw)
{
    __shared__ float As[16][16];
    __shared__ float Ws[16][17];
    int tx = threadIdx.x, ty = threadIdx.y;
    int m = blockIdx.y * 16 + ty;
    int n = blockIdx.x * 16 + tx;
    float acc = 0.f;
    for (int k0 = 0; k0 < K; k0 += 16) {
        As[ty][tx] = (m < M) ? A[m * K + k0 + tx] : 0.f;
        int nn = blockIdx.x * 16 + ty;
        Ws[ty][tx] = (nn < N) ? W[(size_t)nn * ldw + k0 + tx] : 0.f;
        __syncthreads();
#pragma unroll
        for (int kk = 0; kk < 16; kk++) acc += As[ty][kk] * Ws[tx][kk];
        __syncthreads();
    }
    if (m < M && n < N) {
        float b = bias ? bias[n] : 0.f;
        out[m * N + n] = acc + b;
    }
}

// ---------------- big GEMM over edge rows: M=32768 (grid.y*128), N=256 -----
// MODE 0: out = A@W^T + bias[n]                        (edge projection)
// MODE 1: out = lrelu(A@W^T + ai[b,i,n] + aj[b,j,n]) * mask[m] + A[m,n]
#define BM 128
#define BN_ 128
#define BK 16
template<int MODE>
__global__ void __launch_bounds__(256)
big_gemm(const float* __restrict__ A, const float* __restrict__ W,
         int K, int ldw,
         const float* __restrict__ bias,
         const float* __restrict__ ai, const float* __restrict__ aj,
         const float* __restrict__ mask, float* __restrict__ out)
{
    __shared__ float As[BK][BM + 4];
    __shared__ float Bs[BK][BN_ + 4];
    int tid = threadIdx.x;
    int tx = tid & 15, ty = tid >> 4;
    int ty8 = ty * 8, tx8 = tx * 8;
    int mbase = blockIdx.y * BM;
    int nbase = blockIdx.x * BN_;

    int lr = tid >> 2;            // 0..63
    int lk = (tid & 3) << 2;      // 0,4,8,12

    float acc[8][8];
#pragma unroll
    for (int r = 0; r < 8; r++)
#pragma unroll
        for (int c = 0; c < 8; c++) acc[r][c] = 0.f;

    for (int kt = 0; kt < K; kt += BK) {
#pragma unroll
        for (int it = 0; it < 2; ++it) {
            int row = lr + it * 64;
            float4 av = *(const float4*)&A[(size_t)(mbase + row) * K + kt + lk];
            As[lk + 0][row] = av.x; As[lk + 1][row] = av.y;
            As[lk + 2][row] = av.z; As[lk + 3][row] = av.w;
            float4 wv = *(const float4*)&W[(size_t)(nbase + row) * ldw + kt + lk];
            Bs[lk + 0][row] = wv.x; Bs[lk + 1][row] = wv.y;
            Bs[lk + 2][row] = wv.z; Bs[lk + 3][row] = wv.w;
        }
        __syncthreads();
#pragma unroll
        for (int k = 0; k < BK; k++) {
            float4 a0 = *(const float4*)&As[k][ty8];
            float4 a1 = *(const float4*)&As[k][ty8 + 4];
            float4 b0 = *(const float4*)&Bs[k][tx8];
            float4 b1 = *(const float4*)&Bs[k][tx8 + 4];
            float ar[8] = {a0.x, a0.y, a0.z, a0.w, a1.x, a1.y, a1.z, a1.w};
            float br[8] = {b0.x, b0.y, b0.z, b0.w, b1.x, b1.y, b1.z, b1.w};
#pragma unroll
            for (int r = 0; r < 8; r++)
#pragma unroll
                for (int c = 0; c < 8; c++) acc[r][c] += ar[r] * br[c];
        }
        __syncthreads();
    }

    // epilogue
#pragma unroll
    for (int r = 0; r < 8; r++) {
        int m = mbase + ty8 + r;
        if (MODE == 0) {
#pragma unroll
            for (int c = 0; c < 8; c++) acc[r][c] += bias[nbase + tx8 + c];
        } else {
            int b = m >> 14;
            int ij = m & 16383;
            int i = ij >> 7;
            int j = ij & 127;
            float mv = mask[m];
            const float* aip = &ai[(size_t)((b << 7) + i) * 256 + nbase + tx8];
            const float* ajp = &aj[(size_t)((b << 7) + j) * 256 + nbase + tx8];
            const float* res = &A[(size_t)m * 256 + nbase + tx8];
            float4 ai0 = *(const float4*)&aip[0], ai1 = *(const float4*)&aip[4];
            float4 aj0 = *(const float4*)&ajp[0], aj1 = *(const float4*)&ajp[4];
            float4 re0 = *(const float4*)&res[0], re1 = *(const float4*)&res[4];
            float aiv[8] = {ai0.x, ai0.y, ai0.z, ai0.w, ai1.x, ai1.y, ai1.z, ai1.w};
            float ajv[8] = {aj0.x, aj0.y, aj0.z, aj0.w, aj1.x, aj1.y, aj1.z, aj1.w};
            float rev[8] = {re0.x, re0.y, re0.z, re0.w, re1.x, re1.y, re1.z, re1.w};
#pragma unroll
            for (int c = 0; c < 8; c++) {
                float v = acc[r][c] + aiv[c] + ajv[c];
                v = v > 0.f ? v : ALPHA * v;
                acc[r][c] = v * mv + rev[c];
            }
        }
        float* op = &out[(size_t)m * 256 + nbase + tx8];
        *(float4*)&op[0] = make_float4(acc[r][0], acc[r][1], acc[r][2], acc[r][3]);
        *(float4*)&op[4] = make_float4(acc[r][4], acc[r][5], acc[r][6], acc[r][7]);
    }
}

// ---------------- per-row LayerNorm on edges (in place) + dot with v -------
__global__ void ln_edge_kernel(float* __restrict__ e, const float* __restrict__ g,
                               const float* __restrict__ bt, const float* __restrict__ v,
                               float* __restrict__ dotv)
{
    int warp = threadIdx.x >> 5, lane = threadIdx.x & 31;
    int row = blockIdx.x * 8 + warp;
    float* rp = e + (size_t)row * 256;
    float x[8];
    float su = 0.f, sq = 0.f;
#pragma unroll
    for (int q = 0; q < 8; q++) {
        x[q] = rp[lane + q * 32];
        su += x[q]; sq += x[q] * x[q];
    }
#pragma unroll
    for (int o = 16; o; o >>= 1) {
        su += __shfl_xor_sync(0xffffffffu, su, o);
        sq += __shfl_xor_sync(0xffffffffu, sq, o);
    }
    float mean = su * (1.f / 256.f);
    float var = sq * (1.f / 256.f) - mean * mean;
    float inv = rsqrtf(var + LN_EPS);
    float dv = 0.f;
#pragma unroll
    for (int q = 0; q < 8; q++) {
        int c = lane + q * 32;
        float y = (x[q] - mean) * inv * g[c] + bt[c];
        rp[c] = y;
        dv += y * v[c];
    }
#pragma unroll
    for (int o = 16; o; o >>= 1) dv += __shfl_xor_sync(0xffffffffu, dv, o);
    if (lane == 0) dotv[row] = dv;
}

// ---------------- v = Wbp^T ub, w = Wfp^T ub -------------------------------
__global__ void vw_kernel(const float* __restrict__ Wbp, const float* __restrict__ Wfp,
                          const float* __restrict__ ub, float* __restrict__ v,
                          float* __restrict__ w)
{
    int k = threadIdx.x;
    float a = 0.f, b = 0.f;
    for (int c = 0; c < 256; c++) {
        float u = ub[c];
        a += u * Wbp[c * 256 + k];
        b += u * Wfp[c * 256 + k];
    }
    v[k] = a; w[k] = b;
}

// ---------------- s[b,n] = nodes[b,n]·w ------------------------------------
__global__ void s_kernel(const float* __restrict__ nodes, const float* __restrict__ w,
                         float* __restrict__ s)
{
    int t = threadIdx.x;  // 256 rows
    float acc = 0.f;
    const float* rp = nodes + (size_t)t * 256;
    for (int c = 0; c < 256; c++) acc += rp[c] * w[c];
    s[t] = acc;
}

// ---------------- attention + node update (LN fused) -----------------------
__global__ void __launch_bounds__(256)
attn_kernel(const float* __restrict__ dotv, const float* __restrict__ s,
            const float* __restrict__ nf, const float* __restrict__ mask,
            const float* __restrict__ nodes_old, const float* __restrict__ g,
            const float* __restrict__ bt, float* __restrict__ nodes_new)
{
    int bi = blockIdx.x;
    int b = bi >> 7, i = bi & 127;
    int t = threadIdx.x;
    __shared__ float sm_a[128];
    __shared__ float sred1[8], sred2[8];
    __shared__ float sm_m, sm_sum, sm_mean, sm_inv;

    if (t < 128) {
        int j = t;
        float mv = mask[b * 16384 + i * 128 + j];
        float r;
        if (mv > 0.f) {
            float dv = dotv[b * 16384 + j * 128 + i];
            r = dv + s[b * 128 + i] + s[b * 128 + j];
            r = r > 0.f ? r : ALPHA * r;
        } else {
            r = NEG_BIG;
        }
        sm_a[j] = r;
    }
    __syncthreads();
    if (t < 32) {
        float m = fmaxf(fmaxf(sm_a[t], sm_a[t + 32]), fmaxf(sm_a[t + 64], sm_a[t + 96]));
#pragma unroll
        for (int o = 16; o; o >>= 1) m = fmaxf(m, __shfl_xor_sync(0xffffffffu, m, o));
        if (t == 0) sm_m = m;
    }
    __syncthreads();
    if (t < 128) sm_a[t] = expf(sm_a[t] - sm_m);
    __syncthreads();
    if (t < 32) {
        float su = sm_a[t] + sm_a[t + 32] + sm_a[t + 64] + sm_a[t + 96];
#pragma unroll
        for (int o = 16; o; o >>= 1) su += __shfl_xor_sync(0xffffffffu, su, o);
        if (t == 0) sm_sum = su;
    }
    __syncthreads();
    float inv_sum = 1.f / sm_sum;

    int c = t;
    float acc = 0.f;
    const float* nfb = nf + (size_t)b * Nn * Cc + c;
#pragma unroll 4
    for (int j = 0; j < 128; j++) acc += sm_a[j] * nfb[(size_t)j * Cc];
    acc *= inv_sum;
    float h = (acc > 0.f ? acc : ALPHA * acc) + nodes_old[(size_t)(b * 128 + i) * 256 + c];

    // block LN over 256
    int lane = t & 31, wp = t >> 5;
    float su = h, sq = h * h;
#pragma unroll
    for (int o = 16; o; o >>= 1) {
        su += __shfl_xor_sync(0xffffffffu, su, o);
        sq += __shfl_xor_sync(0xffffffffu, sq, o);
    }
    if (lane == 0) { sred1[wp] = su; sred2[wp] = sq; }
    __syncthreads();
    if (t == 0) {
        float S = 0.f, Q = 0.f;
#pragma unroll
        for (int w2 = 0; w2 < 8; w2++) { S += sred1[w2]; Q += sred2[w2]; }
        float mean = S * (1.f / 256.f);
        float var = Q * (1.f / 256.f) - mean * mean;
        sm_mean = mean;
        sm_inv = rsqrtf(var + LN_EPS);
    }
    __syncthreads();
    nodes_new[(size_t)(b * 128 + i) * 256 + c] = (h - sm_mean) * sm_inv * g[c] + bt[c];
}

// ---------------- edge logits: out[row,k] = e[row]·ecW[k] + ecb[k] ---------
__global__ void edge_logits_kernel(const float* __restrict__ e, const float* __restrict__ W,
                                   const float* __restrict__ bias, float* __restrict__ out)
{
    int warp = threadIdx.x >> 5, lane = threadIdx.x & 31;
    int row = blockIdx.x * 8 + warp;
    const float* rp = e + (size_t)row * 256;
    float x[8];
#pragma unroll
    for (int q = 0; q < 8; q++) x[q] = rp[lane + q * 32];
#pragma unroll
    for (int k = 0; k < KE_; k++) {
        float acc = 0.f;
#pragma unroll
        for (int q = 0; q < 8; q++) acc += x[q] * W[k * 256 + lane + q * 32];
#pragma unroll
        for (int o = 16; o; o >>= 1) acc += __shfl_xor_sync(0xffffffffu, acc, o);
        if (lane == 0) out[(size_t)row * KE_ + k] = acc + bias[k];
    }
}

// ---------------- host ------------------------------------------------------
extern "C" void kernel_launch(void* const* d_in, const int* in_sizes, int n_in,
                              void* d_out, int out_size)
{
    const float* nodes_in = (const float*)d_in[0];
    const float* edges_in = (const float*)d_in[1];
    const float* adj      = (const float*)d_in[2];
    const float* pnW = (const float*)d_in[3];
    const float* pnb = (const float*)d_in[4];
    const float* peW = (const float*)d_in[5];
    const float* peb = (const float*)d_in[6];
    const float* Wb  = (const float*)d_in[7];
    const float* Wbp = (const float*)d_in[8];
    const float* Wfp = (const float*)d_in[9];
    const float* ub  = (const float*)d_in[10];
    const float* Wf  = (const float*)d_in[11];
    const float* eln_g = (const float*)d_in[12];
    const float* eln_b = (const float*)d_in[13];
    const float* nln_g = (const float*)d_in[14];
    const float* nln_b = (const float*)d_in[15];
    const float* ncW = (const float*)d_in[16];
    const float* ncb = (const float*)d_in[17];
    const float* ecW = (const float*)d_in[18];
    const float* ecb = (const float*)d_in[19];

    float *eA, *eB, *n0, *n1, *ai_, *aj_, *nf_, *s_, *v_, *w_, *dv_;
    cudaGetSymbolAddress((void**)&eA, g_eA);
    cudaGetSymbolAddress((void**)&eB, g_eB);
    cudaGetSymbolAddress((void**)&n0, g_n0);
    cudaGetSymbolAddress((void**)&n1, g_n1);
    cudaGetSymbolAddress((void**)&ai_, g_ai);
    cudaGetSymbolAddress((void**)&aj_, g_aj);
    cudaGetSymbolAddress((void**)&nf_, g_nf);
    cudaGetSymbolAddress((void**)&s_, g_s);
    cudaGetSymbolAddress((void**)&v_, g_v);
    cudaGetSymbolAddress((void**)&w_, g_w);
    cudaGetSymbolAddress((void**)&dv_, g_dotv);

    float* ecur = eA; float* enxt = eB;
    float* ncur = n0; float* nnxt = n1;

    dim3 bs(16, 16);

    // initial projections
    gemm_small<<<dim3(16, 16), bs>>>(nodes_in, pnW, pnb, ncur, 256, 256, 128, 128);
    big_gemm<0><<<dim3(2, 256), 256>>>(edges_in, peW, 64, 64, peb,
                                       nullptr, nullptr, nullptr, ecur);

    for (int l = 0; l < 3; l++) {
        const float* Wb_l  = Wb  + (size_t)l * 256 * 768;
        const float* Wbp_l = Wbp + (size_t)l * 65536;
        const float* Wfp_l = Wfp + (size_t)l * 65536;
        const float* ub_l  = ub  + l * 256;
        const float* Wf_l  = Wf  + (size_t)l * 65536;

        vw_kernel<<<1, 256>>>(Wbp_l, Wfp_l, ub_l, v_, w_);
        gemm_small<<<dim3(16, 16), bs>>>(ncur, Wb_l,        nullptr, ai_, 256, 256, 256, 768);
        gemm_small<<<dim3(16, 16), bs>>>(ncur, Wb_l + 512,  nullptr, aj_, 256, 256, 256, 768);
        gemm_small<<<dim3(16, 16), bs>>>(ncur, Wf_l,        nullptr, nf_, 256, 256, 256, 256);
        s_kernel<<<1, 256>>>(ncur, w_, s_);

        big_gemm<1><<<dim3(2, 256), 256>>>(ecur, Wb_l + 256, 256, 768, nullptr,
                                           ai_, aj_, adj, enxt);
        ln_edge_kernel<<<4096, 256>>>(enxt, eln_g + l * 256, eln_b + l * 256, v_, dv_);
        attn_kernel<<<256, 256>>>(dv_, s_, nf_, adj, ncur,
                                  nln_g + l * 256, nln_b + l * 256, nnxt);

        float* te = ecur; ecur = enxt; enxt = te;
        float* tn = ncur; ncur = nnxt; nnxt = tn;
    }

    float* out = (float*)d_out;
    cudaMemcpyAsync(out, ncur, (size_t)NODES_SZ * sizeof(float), cudaMemcpyDeviceToDevice);
    cudaMemcpyAsync(out + NODES_SZ, ecur, (size_t)EDGES_SZ * sizeof(float),
                    cudaMemcpyDeviceToDevice);
    gemm_small<<<dim3(7, 16), bs>>>(ncur, ncW, ncb, out + NODES_SZ + EDGES_SZ,
                                    256, KN_, 256, 256);
    edge_logits_kernel<<<4096, 256>>>(ecur, ecW, ecb,
                                      out + NODES_SZ + EDGES_SZ + 256 * KN_);
}

// round 3
// speedup vs baseline: 1.4055x; 1.4055x over previous
#include <cuda_runtime.h>

#define Bb 2
#define Nn 128
#define Cc 256
#define BN2 (Bb*Nn*Nn)        // 32768 edge rows
#define NODES_SZ (Bb*Nn*Cc)   // 65536
#define EDGES_SZ (BN2*Cc)     // 8388608
#define KN_ 101
#define KE_ 7
#define ALPHA 0.2f
#define LN_EPS 1e-5f
#define NEG_BIG (-1e30f)

// ---------------- scratch (device globals: allocation-free) ----------------
__device__ float g_eA[EDGES_SZ];
__device__ float g_eB[EDGES_SZ];
__device__ float g_n0[NODES_SZ];
__device__ float g_n1[NODES_SZ];
__device__ float g_ai[NODES_SZ];
__device__ float g_aj[NODES_SZ];
__device__ float g_nf[NODES_SZ];
__device__ float g_s[Bb*Nn];
__device__ float g_v[Cc];
__device__ float g_w[Cc];
__device__ float g_dotv[BN2];

// packed f32x2 FMA: d = a*b + d elementwise on two packed fp32
__device__ __forceinline__ void ffma2(unsigned long long& d, unsigned long long a,
                                      unsigned long long b)
{
    asm("fma.rn.f32x2 %0, %1, %2, %0;" : "+l"(d) : "l"(a), "l"(b));
}
__device__ __forceinline__ float2 ull2f2(unsigned long long u)
{
    float2 f;
    asm("mov.b64 {%0,%1}, %2;" : "=f"(f.x), "=f"(f.y) : "l"(u));
    return f;
}

// ---------------- small generic GEMM: out[m,n] = A[m,:]·W[n,:] + bias ------
__global__ void gemm_small(const float* __restrict__ A, const float* __restrict__ W,
                           const float* __restrict__ bias, float* __restrict__ out,
                           int M, int N, int K, int ldw)
{
    __shared__ float As[16][16];
    __shared__ float Ws[16][17];
    int tx = threadIdx.x, ty = threadIdx.y;
    int m = blockIdx.y * 16 + ty;
    int n = blockIdx.x * 16 + tx;
    float acc = 0.f;
    for (int k0 = 0; k0 < K; k0 += 16) {
        As[ty][tx] = (m < M) ? A[m * K + k0 + tx] : 0.f;
        int nn = blockIdx.x * 16 + ty;
        Ws[ty][tx] = (nn < N) ? W[(size_t)nn * ldw + k0 + tx] : 0.f;
        __syncthreads();
#pragma unroll
        for (int kk = 0; kk < 16; kk++) acc += As[ty][kk] * Ws[tx][kk];
        __syncthreads();
    }
    if (m < M && n < N) {
        float b = bias ? bias[n] : 0.f;
        out[m * N + n] = acc + b;
    }
}

// ---- merged node GEMMs: z=0 -> ai (Wb1), z=1 -> aj (Wb3), z=2 -> nf (Wf) --
__global__ void node3_gemm(const float* __restrict__ A, const float* __restrict__ Wb_l,
                           const float* __restrict__ Wf_l,
                           float* __restrict__ ai, float* __restrict__ aj,
                           float* __restrict__ nf)
{
    __shared__ float As[16][16];
    __shared__ float Ws[16][17];
    int z = blockIdx.z;
    const float* W = (z == 0) ? Wb_l : (z == 1) ? (Wb_l + 512) : Wf_l;
    int ldw = (z == 2) ? 256 : 768;
    float* out = (z == 0) ? ai : (z == 1) ? aj : nf;
    int tx = threadIdx.x, ty = threadIdx.y;
    int m = blockIdx.y * 16 + ty;
    int n = blockIdx.x * 16 + tx;
    float acc = 0.f;
    for (int k0 = 0; k0 < 256; k0 += 16) {
        As[ty][tx] = A[m * 256 + k0 + tx];
        int nn = blockIdx.x * 16 + ty;
        Ws[ty][tx] = W[(size_t)nn * ldw + k0 + tx];
        __syncthreads();
#pragma unroll
        for (int kk = 0; kk < 16; kk++) acc += As[ty][kk] * Ws[tx][kk];
        __syncthreads();
    }
    out[m * 256 + n] = acc;
}

// ---------------- big GEMM over edge rows: M=32768, N=256, f32x2 core ------
// MODE 0: out = A@W^T + bias[n]                        (edge projection)
// MODE 1: out = lrelu(A@W^T + ai[b,i,n] + aj[b,j,n]) * mask[m] + A[m,n]
#define BM 128
#define BN_ 128
#define BK 16
template<int MODE>
__global__ void __launch_bounds__(256, 2)
big_gemm(const float* __restrict__ A, const float* __restrict__ W,
         int K, int ldw,
         const float* __restrict__ bias,
         const float* __restrict__ ai, const float* __restrict__ aj,
         const float* __restrict__ mask, float* __restrict__ out)
{
    // A tile stored DUPLICATED: As2[k][2m]=As2[k][2m+1]=a[m]  (for f32x2 bcast)
    __shared__ float As2[BK][2 * BM + 8];
    __shared__ float Bs[BK][BN_ + 4];
    int tid = threadIdx.x;
    int tx = tid & 15, ty = tid >> 4;
    int ty8 = ty * 8, tx8 = tx * 8;
    int mbase = blockIdx.y * BM;
    int nbase = blockIdx.x * BN_;

    int lr = tid >> 2;            // 0..63
    int lk = (tid & 3) << 2;      // 0,4,8,12

    unsigned long long acc2[8][4];
#pragma unroll
    for (int r = 0; r < 8; r++)
#pragma unroll
        for (int c = 0; c < 4; c++) acc2[r][c] = 0ull;

    for (int kt = 0; kt < K; kt += BK) {
#pragma unroll
        for (int it = 0; it < 2; ++it) {
            int row = lr + it * 64;
            float4 av = *(const float4*)&A[(size_t)(mbase + row) * K + kt + lk];
            *(float2*)&As2[lk + 0][2 * row] = make_float2(av.x, av.x);
            *(float2*)&As2[lk + 1][2 * row] = make_float2(av.y, av.y);
            *(float2*)&As2[lk + 2][2 * row] = make_float2(av.z, av.z);
            *(float2*)&As2[lk + 3][2 * row] = make_float2(av.w, av.w);
            float4 wv = *(const float4*)&W[(size_t)(nbase + row) * ldw + kt + lk];
            Bs[lk + 0][row] = wv.x; Bs[lk + 1][row] = wv.y;
            Bs[lk + 2][row] = wv.z; Bs[lk + 3][row] = wv.w;
        }
        __syncthreads();
#pragma unroll
        for (int k = 0; k < BK; k++) {
            // a: 4 × 16B loads -> 8 duplicated pairs (rows ty8..ty8+7)
            double2 A0 = *(const double2*)&As2[k][2 * ty8];
            double2 A1 = *(const double2*)&As2[k][2 * ty8 + 4];
            double2 A2 = *(const double2*)&As2[k][2 * ty8 + 8];
            double2 A3 = *(const double2*)&As2[k][2 * ty8 + 12];
            // b: 2 × 16B loads -> 4 packed column pairs
            double2 B0 = *(const double2*)&Bs[k][tx8];
            double2 B1 = *(const double2*)&Bs[k][tx8 + 4];
            unsigned long long ar[8] = {
                __double_as_longlong(A0.x), __double_as_longlong(A0.y),
                __double_as_longlong(A1.x), __double_as_longlong(A1.y),
                __double_as_longlong(A2.x), __double_as_longlong(A2.y),
                __double_as_longlong(A3.x), __double_as_longlong(A3.y)};
            unsigned long long br[4] = {
                __double_as_longlong(B0.x), __double_as_longlong(B0.y),
                __double_as_longlong(B1.x), __double_as_longlong(B1.y)};
#pragma unroll
            for (int r = 0; r < 8; r++)
#pragma unroll
                for (int c = 0; c < 4; c++) ffma2(acc2[r][c], ar[r], br[c]);
        }
        __syncthreads();
    }

    // epilogue
#pragma unroll
    for (int r = 0; r < 8; r++) {
        int m = mbase + ty8 + r;
        float accf[8];
#pragma unroll
        for (int c = 0; c < 4; c++) {
            float2 f = ull2f2(acc2[r][c]);
            accf[2 * c] = f.x; accf[2 * c + 1] = f.y;
        }
        if (MODE == 0) {
#pragma unroll
            for (int c = 0; c < 8; c++) accf[c] += bias[nbase + tx8 + c];
        } else {
            int b = m >> 14;
            int ij = m & 16383;
            int i = ij >> 7;
            int j = ij & 127;
            float mv = mask[m];
            const float* aip = &ai[(size_t)((b << 7) + i) * 256 + nbase + tx8];
            const float* ajp = &aj[(size_t)((b << 7) + j) * 256 + nbase + tx8];
            const float* res = &A[(size_t)m * 256 + nbase + tx8];
            float4 ai0 = *(const float4*)&aip[0], ai1 = *(const float4*)&aip[4];
            float4 aj0 = *(const float4*)&ajp[0], aj1 = *(const float4*)&ajp[4];
            float4 re0 = *(const float4*)&res[0], re1 = *(const float4*)&res[4];
            float aiv[8] = {ai0.x, ai0.y, ai0.z, ai0.w, ai1.x, ai1.y, ai1.z, ai1.w};
            float ajv[8] = {aj0.x, aj0.y, aj0.z, aj0.w, aj1.x, aj1.y, aj1.z, aj1.w};
            float rev[8] = {re0.x, re0.y, re0.z, re0.w, re1.x, re1.y, re1.z, re1.w};
#pragma unroll
            for (int c = 0; c < 8; c++) {
                float v = accf[c] + aiv[c] + ajv[c];
                v = v > 0.f ? v : ALPHA * v;
                accf[c] = v * mv + rev[c];
            }
        }
        float* op = &out[(size_t)m * 256 + nbase + tx8];
        *(float4*)&op[0] = make_float4(accf[0], accf[1], accf[2], accf[3]);
        *(float4*)&op[4] = make_float4(accf[4], accf[5], accf[6], accf[7]);
    }
}

// ---------------- per-row LayerNorm on edges (in place) + dot with v -------
__global__ void ln_edge_kernel(float* __restrict__ e, const float* __restrict__ g,
                               const float* __restrict__ bt, const float* __restrict__ v,
                               float* __restrict__ dotv)
{
    int warp = threadIdx.x >> 5, lane = threadIdx.x & 31;
    int row = blockIdx.x * 8 + warp;
    float* rp = e + (size_t)row * 256;
    float x[8];
    float su = 0.f, sq = 0.f;
#pragma unroll
    for (int q = 0; q < 8; q++) {
        x[q] = rp[lane + q * 32];
        su += x[q]; sq += x[q] * x[q];
    }
#pragma unroll
    for (int o = 16; o; o >>= 1) {
        su += __shfl_xor_sync(0xffffffffu, su, o);
        sq += __shfl_xor_sync(0xffffffffu, sq, o);
    }
    float mean = su * (1.f / 256.f);
    float var = sq * (1.f / 256.f) - mean * mean;
    float inv = rsqrtf(var + LN_EPS);
    float dv = 0.f;
#pragma unroll
    for (int q = 0; q < 8; q++) {
        int c = lane + q * 32;
        float y = (x[q] - mean) * inv * g[c] + bt[c];
        rp[c] = y;
        dv += y * v[c];
    }
#pragma unroll
    for (int o = 16; o; o >>= 1) dv += __shfl_xor_sync(0xffffffffu, dv, o);
    if (lane == 0) dotv[row] = dv;
}

// ---------------- v = Wbp^T ub, w = Wfp^T ub -------------------------------
__global__ void vw_kernel(const float* __restrict__ Wbp, const float* __restrict__ Wfp,
                          const float* __restrict__ ub, float* __restrict__ v,
                          float* __restrict__ w)
{
    int k = threadIdx.x;
    float a = 0.f, b = 0.f;
    for (int c = 0; c < 256; c++) {
        float u = ub[c];
        a += u * Wbp[c * 256 + k];
        b += u * Wfp[c * 256 + k];
    }
    v[k] = a; w[k] = b;
}

// ---------------- s[b,n] = nodes[b,n]·w ------------------------------------
__global__ void s_kernel(const float* __restrict__ nodes, const float* __restrict__ w,
                         float* __restrict__ s)
{
    int t = threadIdx.x;  // 256 rows
    float acc = 0.f;
    const float* rp = nodes + (size_t)t * 256;
    for (int c = 0; c < 256; c++) acc += rp[c] * w[c];
    s[t] = acc;
}

// ---------------- attention + node update (LN fused) -----------------------
__global__ void __launch_bounds__(256)
attn_kernel(const float* __restrict__ dotv, const float* __restrict__ s,
            const float* __restrict__ nf, const float* __restrict__ mask,
            const float* __restrict__ nodes_old, const float* __restrict__ g,
            const float* __restrict__ bt, float* __restrict__ nodes_new)
{
    int bi = blockIdx.x;
    int b = bi >> 7, i = bi & 127;
    int t = threadIdx.x;
    __shared__ float sm_a[128];
    __shared__ float sred1[8], sred2[8];
    __shared__ float sm_m, sm_sum, sm_mean, sm_inv;

    if (t < 128) {
        int j = t;
        float mv = mask[b * 16384 + i * 128 + j];
        float r;
        if (mv > 0.f) {
            float dv = dotv[b * 16384 + j * 128 + i];
            r = dv + s[b * 128 + i] + s[b * 128 + j];
            r = r > 0.f ? r : ALPHA * r;
        } else {
            r = NEG_BIG;
        }
        sm_a[j] = r;
    }
    __syncthreads();
    if (t < 32) {
        float m = fmaxf(fmaxf(sm_a[t], sm_a[t + 32]), fmaxf(sm_a[t + 64], sm_a[t + 96]));
#pragma unroll
        for (int o = 16; o; o >>= 1) m = fmaxf(m, __shfl_xor_sync(0xffffffffu, m, o));
        if (t == 0) sm_m = m;
    }
    __syncthreads();
    if (t < 128) sm_a[t] = expf(sm_a[t] - sm_m);
    __syncthreads();
    if (t < 32) {
        float su = sm_a[t] + sm_a[t + 32] + sm_a[t + 64] + sm_a[t + 96];
#pragma unroll
        for (int o = 16; o; o >>= 1) su += __shfl_xor_sync(0xffffffffu, su, o);
        if (t == 0) sm_sum = su;
    }
    __syncthreads();
    float inv_sum = 1.f / sm_sum;

    int c = t;
    float acc = 0.f;
    const float* nfb = nf + (size_t)b * Nn * Cc + c;
#pragma unroll 4
    for (int j = 0; j < 128; j++) acc += sm_a[j] * nfb[(size_t)j * Cc];
    acc *= inv_sum;
    float h = (acc > 0.f ? acc : ALPHA * acc) + nodes_old[(size_t)(b * 128 + i) * 256 + c];

    // block LN over 256
    int lane = t & 31, wp = t >> 5;
    float su = h, sq = h * h;
#pragma unroll
    for (int o = 16; o; o >>= 1) {
        su += __shfl_xor_sync(0xffffffffu, su, o);
        sq += __shfl_xor_sync(0xffffffffu, sq, o);
    }
    if (lane == 0) { sred1[wp] = su; sred2[wp] = sq; }
    __syncthreads();
    if (t == 0) {
        float S = 0.f, Q = 0.f;
#pragma unroll
        for (int w2 = 0; w2 < 8; w2++) { S += sred1[w2]; Q += sred2[w2]; }
        float mean = S * (1.f / 256.f);
        float var = Q * (1.f / 256.f) - mean * mean;
        sm_mean = mean;
        sm_inv = rsqrtf(var + LN_EPS);
    }
    __syncthreads();
    nodes_new[(size_t)(b * 128 + i) * 256 + c] = (h - sm_mean) * sm_inv * g[c] + bt[c];
}

// ---------------- edge logits: out[row,k] = e[row]·ecW[k] + ecb[k] ---------
__global__ void edge_logits_kernel(const float* __restrict__ e, const float* __restrict__ W,
                                   const float* __restrict__ bias, float* __restrict__ out)
{
    int warp = threadIdx.x >> 5, lane = threadIdx.x & 31;
    int row = blockIdx.x * 8 + warp;
    const float* rp = e + (size_t)row * 256;
    float x[8];
#pragma unroll
    for (int q = 0; q < 8; q++) x[q] = rp[lane + q * 32];
#pragma unroll
    for (int k = 0; k < KE_; k++) {
        float acc = 0.f;
#pragma unroll
        for (int q = 0; q < 8; q++) acc += x[q] * W[k * 256 + lane + q * 32];
#pragma unroll
        for (int o = 16; o; o >>= 1) acc += __shfl_xor_sync(0xffffffffu, acc, o);
        if (lane == 0) out[(size_t)row * KE_ + k] = acc + bias[k];
    }
}

// ---------------- host ------------------------------------------------------
extern "C" void kernel_launch(void* const* d_in, const int* in_sizes, int n_in,
                              void* d_out, int out_size)
{
    const float* nodes_in = (const float*)d_in[0];
    const float* edges_in = (const float*)d_in[1];
    const float* adj      = (const float*)d_in[2];
    const float* pnW = (const float*)d_in[3];
    const float* pnb = (const float*)d_in[4];
    const float* peW = (const float*)d_in[5];
    const float* peb = (const float*)d_in[6];
    const float* Wb  = (const float*)d_in[7];
    const float* Wbp = (const float*)d_in[8];
    const float* Wfp = (const float*)d_in[9];
    const float* ub  = (const float*)d_in[10];
    const float* Wf  = (const float*)d_in[11];
    const float* eln_g = (const float*)d_in[12];
    const float* eln_b = (const float*)d_in[13];
    const float* nln_g = (const float*)d_in[14];
    const float* nln_b = (const float*)d_in[15];
    const float* ncW = (const float*)d_in[16];
    const float* ncb = (const float*)d_in[17];
    const float* ecW = (const float*)d_in[18];
    const float* ecb = (const float*)d_in[19];

    float *eA, *eB, *n0, *n1, *ai_, *aj_, *nf_, *s_, *v_, *w_, *dv_;
    cudaGetSymbolAddress((void**)&eA, g_eA);
    cudaGetSymbolAddress((void**)&eB, g_eB);
    cudaGetSymbolAddress((void**)&n0, g_n0);
    cudaGetSymbolAddress((void**)&n1, g_n1);
    cudaGetSymbolAddress((void**)&ai_, g_ai);
    cudaGetSymbolAddress((void**)&aj_, g_aj);
    cudaGetSymbolAddress((void**)&nf_, g_nf);
    cudaGetSymbolAddress((void**)&s_, g_s);
    cudaGetSymbolAddress((void**)&v_, g_v);
    cudaGetSymbolAddress((void**)&w_, g_w);
    cudaGetSymbolAddress((void**)&dv_, g_dotv);

    float* out = (float*)d_out;
    float* out_nodes = out;
    float* out_edges = out + NODES_SZ;

    // ping-pong schedule; layer 2 writes land directly in d_out (no copies)
    float* ebuf[4] = {eA, eB, eA, out_edges};
    float* nbuf[4] = {n0, n1, n0, out_nodes};

    dim3 bs(16, 16);

    // initial projections
    gemm_small<<<dim3(16, 16), bs>>>(nodes_in, pnW, pnb, nbuf[0], 256, 256, 128, 128);
    big_gemm<0><<<dim3(2, 256), 256>>>(edges_in, peW, 64, 64, peb,
                                       nullptr, nullptr, nullptr, ebuf[0]);

    for (int l = 0; l < 3; l++) {
        const float* Wb_l  = Wb  + (size_t)l * 256 * 768;
        const float* Wbp_l = Wbp + (size_t)l * 65536;
        const float* Wfp_l = Wfp + (size_t)l * 65536;
        const float* ub_l  = ub  + l * 256;
        const float* Wf_l  = Wf  + (size_t)l * 65536;
        float* ecur = ebuf[l]; float* enxt = ebuf[l + 1];
        float* ncur = nbuf[l]; float* nnxt = nbuf[l + 1];

        vw_kernel<<<1, 256>>>(Wbp_l, Wfp_l, ub_l, v_, w_);
        node3_gemm<<<dim3(16, 16, 3), bs>>>(ncur, Wb_l, Wf_l, ai_, aj_, nf_);
        s_kernel<<<1, 256>>>(ncur, w_, s_);

        big_gemm<1><<<dim3(2, 256), 256>>>(ecur, Wb_l + 256, 256, 768, nullptr,
                                           ai_, aj_, adj, enxt);
        ln_edge_kernel<<<4096, 256>>>(enxt, eln_g + l * 256, eln_b + l * 256, v_, dv_);
        attn_kernel<<<256, 256>>>(dv_, s_, nf_, adj, ncur,
                                  nln_g + l * 256, nln_b + l * 256, nnxt);
    }

    // final heads read directly from d_out regions
    gemm_small<<<dim3(7, 16), bs>>>(nbuf[3], ncW, ncb, out + NODES_SZ + EDGES_SZ,
                                    256, KN_, 256, 256);
    edge_logits_kernel<<<4096, 256>>>(ebuf[3], ecW, ecb,
                                      out + NODES_SZ + EDGES_SZ + 256 * KN_);
}

// round 4
// speedup vs baseline: 2.1926x; 1.5600x over previous
#include <cuda_runtime.h>

#define Bb 2
#define Nn 128
#define Cc 256
#define BN2 (Bb*Nn*Nn)        // 32768 edge rows
#define NODES_SZ (Bb*Nn*Cc)   // 65536
#define EDGES_SZ (BN2*Cc)     // 8388608
#define KN_ 101
#define KE_ 7
#define ALPHA 0.2f
#define LN_EPS 1e-5f
#define NEG_BIG (-1e30f)

// ---------------- scratch (device globals: allocation-free) ----------------
__device__ float g_eA[EDGES_SZ];
__device__ float g_eB[EDGES_SZ];
__device__ float g_n0[NODES_SZ];
__device__ float g_n1[NODES_SZ];
__device__ float g_ai[NODES_SZ];
__device__ float g_aj[NODES_SZ];
__device__ float g_nf[NODES_SZ];
__device__ float g_s[Bb*Nn];
__device__ float g_v[Cc];
__device__ float g_w[Cc];
__device__ float g_dotv[BN2];

// ---------------- tf32 helpers ---------------------------------------------
__device__ __forceinline__ unsigned f2tf(float f)
{
    unsigned r;
    asm("cvt.rna.tf32.f32 %0, %1;" : "=r"(r) : "f"(f));
    return r;
}
__device__ __forceinline__ void mma16n8k8(float& c0, float& c1, float& c2, float& c3,
                                          unsigned a0, unsigned a1, unsigned a2, unsigned a3,
                                          unsigned b0, unsigned b1)
{
    asm volatile("mma.sync.aligned.m16n8k8.row.col.f32.tf32.tf32.f32 "
                 "{%0,%1,%2,%3}, {%4,%5,%6,%7}, {%8,%9}, {%0,%1,%2,%3};"
                 : "+f"(c0), "+f"(c1), "+f"(c2), "+f"(c3)
                 : "r"(a0), "r"(a1), "r"(a2), "r"(a3), "r"(b0), "r"(b1));
}

// ---------------- small generic GEMM: out[m,n] = A[m,:]·W[n,:] + bias ------
__global__ void gemm_small(const float* __restrict__ A, const float* __restrict__ W,
                           const float* __restrict__ bias, float* __restrict__ out,
                           int M, int N, int K, int ldw)
{
    __shared__ float As[16][16];
    __shared__ float Ws[16][17];
    int tx = threadIdx.x, ty = threadIdx.y;
    int m = blockIdx.y * 16 + ty;
    int n = blockIdx.x * 16 + tx;
    float acc = 0.f;
    for (int k0 = 0; k0 < K; k0 += 16) {
        As[ty][tx] = (m < M) ? A[m * K + k0 + tx] : 0.f;
        int nn = blockIdx.x * 16 + ty;
        Ws[ty][tx] = (nn < N) ? W[(size_t)nn * ldw + k0 + tx] : 0.f;
        __syncthreads();
#pragma unroll
        for (int kk = 0; kk < 16; kk++) acc += As[ty][kk] * Ws[tx][kk];
        __syncthreads();
    }
    if (m < M && n < N) {
        float b = bias ? bias[n] : 0.f;
        out[m * N + n] = acc + b;
    }
}

// ---- merged node GEMMs: z=0 -> ai (Wb1), z=1 -> aj (Wb3), z=2 -> nf (Wf) --
__global__ void node3_gemm(const float* __restrict__ A, const float* __restrict__ Wb_l,
                           const float* __restrict__ Wf_l,
                           float* __restrict__ ai, float* __restrict__ aj,
                           float* __restrict__ nf)
{
    __shared__ float As[16][16];
    __shared__ float Ws[16][17];
    int z = blockIdx.z;
    const float* W = (z == 0) ? Wb_l : (z == 1) ? (Wb_l + 512) : Wf_l;
    int ldw = (z == 2) ? 256 : 768;
    float* out = (z == 0) ? ai : (z == 1) ? aj : nf;
    int tx = threadIdx.x, ty = threadIdx.y;
    int m = blockIdx.y * 16 + ty;
    int n = blockIdx.x * 16 + tx;
    float acc = 0.f;
    for (int k0 = 0; k0 < 256; k0 += 16) {
        As[ty][tx] = A[m * 256 + k0 + tx];
        int nn = blockIdx.x * 16 + ty;
        Ws[ty][tx] = W[(size_t)nn * ldw + k0 + tx];
        __syncthreads();
#pragma unroll
        for (int kk = 0; kk < 16; kk++) acc += As[ty][kk] * Ws[tx][kk];
        __syncthreads();
    }
    out[m * 256 + n] = acc;
}

// ---------------- edge GEMM, tf32 tensor cores -----------------------------
// out tile 128x128, 8 warps of 64x32, BK=32, K multiple of 32.
// MODE 0: out = A@W^T + bias[n]
// MODE 1: out = lrelu(A@W^T + ai[b,i,n] + aj[b,j,n]) * mask[m] + A[m,n]
#define ESTRIDE 36
template<int MODE>
__global__ void __launch_bounds__(256)
edge_mma(const float* __restrict__ A, const float* __restrict__ W,
         int K, int ldw, const float* __restrict__ bias,
         const float* __restrict__ ai, const float* __restrict__ aj,
         const float* __restrict__ mask, float* __restrict__ out)
{
    __shared__ unsigned As[128 * ESTRIDE];
    __shared__ unsigned Bs[128 * ESTRIDE];
    int tid = threadIdx.x;
    int lane = tid & 31, wid = tid >> 5;
    int warp_m = (wid & 1) * 64;
    int warp_n = (wid >> 1) * 32;
    int mbase = blockIdx.y * 128;
    int nbase = blockIdx.x * 128;

    float c[4][4][4];
#pragma unroll
    for (int mi = 0; mi < 4; mi++)
#pragma unroll
        for (int ni = 0; ni < 4; ni++)
#pragma unroll
            for (int q = 0; q < 4; q++) c[mi][ni][q] = 0.f;

    int lrow = tid >> 1;           // 0..127
    int lk0 = (tid & 1) * 16;      // 0 or 16
    const float* Aptr = A + (size_t)(mbase + lrow) * K + lk0;
    const float* Wptr = W + (size_t)(nbase + lrow) * ldw + lk0;
    unsigned* asw = &As[lrow * ESTRIDE + lk0];
    unsigned* bsw = &Bs[lrow * ESTRIDE + lk0];

    int lg = lane >> 2;   // 0..7
    int lt = lane & 3;    // 0..3

    for (int kt = 0; kt < K; kt += 32) {
#pragma unroll
        for (int q = 0; q < 4; q++) {
            float4 av = *(const float4*)(Aptr + kt + 4 * q);
            float4 wv = *(const float4*)(Wptr + kt + 4 * q);
            uint4 at = make_uint4(f2tf(av.x), f2tf(av.y), f2tf(av.z), f2tf(av.w));
            uint4 bt = make_uint4(f2tf(wv.x), f2tf(wv.y), f2tf(wv.z), f2tf(wv.w));
            *(uint4*)(asw + 4 * q) = at;
            *(uint4*)(bsw + 4 * q) = bt;
        }
        __syncthreads();
#pragma unroll
        for (int k8 = 0; k8 < 4; k8++) {
            int kc = k8 * 8 + lt;
            unsigned af[4][4], bf[4][2];
#pragma unroll
            for (int mi = 0; mi < 4; mi++) {
                int r0 = warp_m + mi * 16 + lg;
                af[mi][0] = As[r0 * ESTRIDE + kc];
                af[mi][1] = As[(r0 + 8) * ESTRIDE + kc];
                af[mi][2] = As[r0 * ESTRIDE + kc + 4];
                af[mi][3] = As[(r0 + 8) * ESTRIDE + kc + 4];
            }
#pragma unroll
            for (int ni = 0; ni < 4; ni++) {
                int n0 = warp_n + ni * 8 + lg;
                bf[ni][0] = Bs[n0 * ESTRIDE + kc];
                bf[ni][1] = Bs[n0 * ESTRIDE + kc + 4];
            }
#pragma unroll
            for (int mi = 0; mi < 4; mi++)
#pragma unroll
                for (int ni = 0; ni < 4; ni++)
                    mma16n8k8(c[mi][ni][0], c[mi][ni][1], c[mi][ni][2], c[mi][ni][3],
                              af[mi][0], af[mi][1], af[mi][2], af[mi][3],
                              bf[ni][0], bf[ni][1]);
        }
        __syncthreads();
    }

    // epilogue: each (mi,ni) fragment covers rows {r0, r0+8}, cols {cc, cc+1}
#pragma unroll
    for (int mi = 0; mi < 4; mi++) {
#pragma unroll
        for (int half = 0; half < 2; half++) {
            int m = mbase + warp_m + mi * 16 + lg + half * 8;
            int b = m >> 14;
            int ij = m & 16383;
            int i = ij >> 7;
            int j = ij & 127;
            float mv = 0.f;
            const float* aip = nullptr;
            const float* ajp = nullptr;
            if (MODE == 1) {
                mv = mask[m];
                aip = &ai[(size_t)((b << 7) + i) * 256];
                ajp = &aj[(size_t)((b << 7) + j) * 256];
            }
#pragma unroll
            for (int ni = 0; ni < 4; ni++) {
                int col = nbase + warp_n + ni * 8 + 2 * lt;
                float v0 = c[mi][ni][2 * half + 0];
                float v1 = c[mi][ni][2 * half + 1];
                if (MODE == 0) {
                    float2 bv = *(const float2*)&bias[col];
                    v0 += bv.x; v1 += bv.y;
                } else {
                    float2 av2 = *(const float2*)&aip[col];
                    float2 aj2 = *(const float2*)&ajp[col];
                    float2 rs2 = *(const float2*)&A[(size_t)m * 256 + col];
                    v0 += av2.x + aj2.x;
                    v1 += av2.y + aj2.y;
                    v0 = (v0 > 0.f ? v0 : ALPHA * v0) * mv + rs2.x;
                    v1 = (v1 > 0.f ? v1 : ALPHA * v1) * mv + rs2.y;
                }
                *(float2*)&out[(size_t)m * 256 + col] = make_float2(v0, v1);
            }
        }
    }
}

// ---------------- per-row LayerNorm on edges (in place) + dot with v -------
__global__ void ln_edge_kernel(float* __restrict__ e, const float* __restrict__ g,
                               const float* __restrict__ bt, const float* __restrict__ v,
                               float* __restrict__ dotv)
{
    int warp = threadIdx.x >> 5, lane = threadIdx.x & 31;
    int row = blockIdx.x * 8 + warp;
    float* rp = e + (size_t)row * 256;
    float x[8];
    float su = 0.f, sq = 0.f;
#pragma unroll
    for (int q = 0; q < 8; q++) {
        x[q] = rp[lane + q * 32];
        su += x[q]; sq += x[q] * x[q];
    }
#pragma unroll
    for (int o = 16; o; o >>= 1) {
        su += __shfl_xor_sync(0xffffffffu, su, o);
        sq += __shfl_xor_sync(0xffffffffu, sq, o);
    }
    float mean = su * (1.f / 256.f);
    float var = sq * (1.f / 256.f) - mean * mean;
    float inv = rsqrtf(var + LN_EPS);
    float dv = 0.f;
#pragma unroll
    for (int q = 0; q < 8; q++) {
        int c = lane + q * 32;
        float y = (x[q] - mean) * inv * g[c] + bt[c];
        rp[c] = y;
        dv += y * v[c];
    }
#pragma unroll
    for (int o = 16; o; o >>= 1) dv += __shfl_xor_sync(0xffffffffu, dv, o);
    if (lane == 0) dotv[row] = dv;
}

// ---------------- v = Wbp^T ub, w = Wfp^T ub -------------------------------
__global__ void vw_kernel(const float* __restrict__ Wbp, const float* __restrict__ Wfp,
                          const float* __restrict__ ub, float* __restrict__ v,
                          float* __restrict__ w)
{
    int k = threadIdx.x;
    float a = 0.f, b = 0.f;
    for (int c = 0; c < 256; c++) {
        float u = ub[c];
        a += u * Wbp[c * 256 + k];
        b += u * Wfp[c * 256 + k];
    }
    v[k] = a; w[k] = b;
}

// ---------------- s[b,n] = nodes[b,n]·w ------------------------------------
__global__ void s_kernel(const float* __restrict__ nodes, const float* __restrict__ w,
                         float* __restrict__ s)
{
    int t = threadIdx.x;  // 256 rows
    float acc = 0.f;
    const float* rp = nodes + (size_t)t * 256;
    for (int c = 0; c < 256; c++) acc += rp[c] * w[c];
    s[t] = acc;
}

// ---------------- attention + node update (LN fused) -----------------------
__global__ void __launch_bounds__(256)
attn_kernel(const float* __restrict__ dotv, const float* __restrict__ s,
            const float* __restrict__ nf, const float* __restrict__ mask,
            const float* __restrict__ nodes_old, const float* __restrict__ g,
            const float* __restrict__ bt, float* __restrict__ nodes_new)
{
    int bi = blockIdx.x;
    int b = bi >> 7, i = bi & 127;
    int t = threadIdx.x;
    __shared__ float sm_a[128];
    __shared__ float sred1[8], sred2[8];
    __shared__ float sm_m, sm_sum, sm_mean, sm_inv;

    if (t < 128) {
        int j = t;
        float mv = mask[b * 16384 + i * 128 + j];
        float r;
        if (mv > 0.f) {
            float dv = dotv[b * 16384 + j * 128 + i];
            r = dv + s[b * 128 + i] + s[b * 128 + j];
            r = r > 0.f ? r : ALPHA * r;
        } else {
            r = NEG_BIG;
        }
        sm_a[j] = r;
    }
    __syncthreads();
    if (t < 32) {
        float m = fmaxf(fmaxf(sm_a[t], sm_a[t + 32]), fmaxf(sm_a[t + 64], sm_a[t + 96]));
#pragma unroll
        for (int o = 16; o; o >>= 1) m = fmaxf(m, __shfl_xor_sync(0xffffffffu, m, o));
        if (t == 0) sm_m = m;
    }
    __syncthreads();
    if (t < 128) sm_a[t] = expf(sm_a[t] - sm_m);
    __syncthreads();
    if (t < 32) {
        float su = sm_a[t] + sm_a[t + 32] + sm_a[t + 64] + sm_a[t + 96];
#pragma unroll
        for (int o = 16; o; o >>= 1) su += __shfl_xor_sync(0xffffffffu, su, o);
        if (t == 0) sm_sum = su;
    }
    __syncthreads();
    float inv_sum = 1.f / sm_sum;

    int c = t;
    float acc = 0.f;
    const float* nfb = nf + (size_t)b * Nn * Cc + c;
#pragma unroll 4
    for (int j = 0; j < 128; j++) acc += sm_a[j] * nfb[(size_t)j * Cc];
    acc *= inv_sum;
    float h = (acc > 0.f ? acc : ALPHA * acc) + nodes_old[(size_t)(b * 128 + i) * 256 + c];

    // block LN over 256
    int lane = t & 31, wp = t >> 5;
    float su = h, sq = h * h;
#pragma unroll
    for (int o = 16; o; o >>= 1) {
        su += __shfl_xor_sync(0xffffffffu, su, o);
        sq += __shfl_xor_sync(0xffffffffu, sq, o);
    }
    if (lane == 0) { sred1[wp] = su; sred2[wp] = sq; }
    __syncthreads();
    if (t == 0) {
        float S = 0.f, Q = 0.f;
#pragma unroll
        for (int w2 = 0; w2 < 8; w2++) { S += sred1[w2]; Q += sred2[w2]; }
        float mean = S * (1.f / 256.f);
        float var = Q * (1.f / 256.f) - mean * mean;
        sm_mean = mean;
        sm_inv = rsqrtf(var + LN_EPS);
    }
    __syncthreads();
    nodes_new[(size_t)(b * 128 + i) * 256 + c] = (h - sm_mean) * sm_inv * g[c] + bt[c];
}

// ---------------- edge logits: out[row,k] = e[row]·ecW[k] + ecb[k] ---------
__global__ void edge_logits_kernel(const float* __restrict__ e, const float* __restrict__ W,
                                   const float* __restrict__ bias, float* __restrict__ out)
{
    int warp = threadIdx.x >> 5, lane = threadIdx.x & 31;
    int row = blockIdx.x * 8 + warp;
    const float* rp = e + (size_t)row * 256;
    float x[8];
#pragma unroll
    for (int q = 0; q < 8; q++) x[q] = rp[lane + q * 32];
#pragma unroll
    for (int k = 0; k < KE_; k++) {
        float acc = 0.f;
#pragma unroll
        for (int q = 0; q < 8; q++) acc += x[q] * W[k * 256 + lane + q * 32];
#pragma unroll
        for (int o = 16; o; o >>= 1) acc += __shfl_xor_sync(0xffffffffu, acc, o);
        if (lane == 0) out[(size_t)row * KE_ + k] = acc + bias[k];
    }
}

// ---------------- host ------------------------------------------------------
extern "C" void kernel_launch(void* const* d_in, const int* in_sizes, int n_in,
                              void* d_out, int out_size)
{
    const float* nodes_in = (const float*)d_in[0];
    const float* edges_in = (const float*)d_in[1];
    const float* adj      = (const float*)d_in[2];
    const float* pnW = (const float*)d_in[3];
    const float* pnb = (const float*)d_in[4];
    const float* peW = (const float*)d_in[5];
    const float* peb = (const float*)d_in[6];
    const float* Wb  = (const float*)d_in[7];
    const float* Wbp = (const float*)d_in[8];
    const float* Wfp = (const float*)d_in[9];
    const float* ub  = (const float*)d_in[10];
    const float* Wf  = (const float*)d_in[11];
    const float* eln_g = (const float*)d_in[12];
    const float* eln_b = (const float*)d_in[13];
    const float* nln_g = (const float*)d_in[14];
    const float* nln_b = (const float*)d_in[15];
    const float* ncW = (const float*)d_in[16];
    const float* ncb = (const float*)d_in[17];
    const float* ecW = (const float*)d_in[18];
    const float* ecb = (const float*)d_in[19];

    float *eA, *eB, *n0, *n1, *ai_, *aj_, *nf_, *s_, *v_, *w_, *dv_;
    cudaGetSymbolAddress((void**)&eA, g_eA);
    cudaGetSymbolAddress((void**)&eB, g_eB);
    cudaGetSymbolAddress((void**)&n0, g_n0);
    cudaGetSymbolAddress((void**)&n1, g_n1);
    cudaGetSymbolAddress((void**)&ai_, g_ai);
    cudaGetSymbolAddress((void**)&aj_, g_aj);
    cudaGetSymbolAddress((void**)&nf_, g_nf);
    cudaGetSymbolAddress((void**)&s_, g_s);
    cudaGetSymbolAddress((void**)&v_, g_v);
    cudaGetSymbolAddress((void**)&w_, g_w);
    cudaGetSymbolAddress((void**)&dv_, g_dotv);

    float* out = (float*)d_out;
    float* out_nodes = out;
    float* out_edges = out + NODES_SZ;

    // ping-pong schedule; layer 2 writes land directly in d_out (no copies)
    float* ebuf[4] = {eA, eB, eA, out_edges};
    float* nbuf[4] = {n0, n1, n0, out_nodes};

    dim3 bs(16, 16);

    // initial projections
    gemm_small<<<dim3(16, 16), bs>>>(nodes_in, pnW, pnb, nbuf[0], 256, 256, 128, 128);
    edge_mma<0><<<dim3(2, 256), 256>>>(edges_in, peW, 64, 64, peb,
                                       nullptr, nullptr, nullptr, ebuf[0]);

    for (int l = 0; l < 3; l++) {
        const float* Wb_l  = Wb  + (size_t)l * 256 * 768;
        const float* Wbp_l = Wbp + (size_t)l * 65536;
        const float* Wfp_l = Wfp + (size_t)l * 65536;
        const float* ub_l  = ub  + l * 256;
        const float* Wf_l  = Wf  + (size_t)l * 65536;
        float* ecur = ebuf[l]; float* enxt = ebuf[l + 1];
        float* ncur = nbuf[l]; float* nnxt = nbuf[l + 1];

        vw_kernel<<<1, 256>>>(Wbp_l, Wfp_l, ub_l, v_, w_);
        node3_gemm<<<dim3(16, 16, 3), bs>>>(ncur, Wb_l, Wf_l, ai_, aj_, nf_);
        s_kernel<<<1, 256>>>(ncur, w_, s_);

        edge_mma<1><<<dim3(2, 256), 256>>>(ecur, Wb_l + 256, 256, 768, nullptr,
                                           ai_, aj_, adj, enxt);
        ln_edge_kernel<<<4096, 256>>>(enxt, eln_g + l * 256, eln_b + l * 256, v_, dv_);
        attn_kernel<<<256, 256>>>(dv_, s_, nf_, adj, ncur,
                                  nln_g + l * 256, nln_b + l * 256, nnxt);
    }

    // final heads read directly from d_out regions
    gemm_small<<<dim3(7, 16), bs>>>(nbuf[3], ncW, ncb, out + NODES_SZ + EDGES_SZ,
                                    256, KN_, 256, 256);
    edge_logits_kernel<<<4096, 256>>>(ebuf[3], ecW, ecb,
                                      out + NODES_SZ + EDGES_SZ + 256 * KN_);
}